// round 3
// baseline (speedup 1.0000x reference)
#include <cuda_runtime.h>
#include <cuda_bf16.h>

// EMA scan y[n] = w*x[n] + (1-w)*y[n-1] over frames (2048, contiguous).
// One CTA (256 threads) per channel; thread t owns frames [4t,4t+4) (chunk0)
// and [1024+4t, 1024+4t+4) (chunk1) -> fully coalesced LDG.128/STG.128.
//
// All segments share the same decay a = (1-w)^4 = q (w is per-channel), so the
// affine scan's multiplier component is deterministic: only the offset 'b' is
// scanned (1 shuffle per Kogge-Stone step per chunk); all needed powers of q
// come from a squaring chain + conditional multiplies.

#define NFRAMES   2048
#define NTHREADS  256
#define NCHANNELS (16 * 8 * 256)

__global__ __launch_bounds__(NTHREADS)
void ema_scan_kernel(const float* __restrict__ in,
                     const float* __restrict__ init_state,
                     const float* __restrict__ wt,
                     float* __restrict__ out)
{
    const int ch   = blockIdx.x;
    const int t    = threadIdx.x;
    const int lane = t & 31;
    const int warp = t >> 5;

    float w = wt[ch & 2047];
    w = fminf(fmaxf(w, 0.0f), 1.0f);
    const float omw = 1.0f - w;

    // Coalesced loads: chunk0 = frames [4t,4t+4), chunk1 = [1024+4t, ...)
    const float4* ip = reinterpret_cast<const float4*>(in + (size_t)ch * NFRAMES);
    float4 x0 = ip[t];
    float4 x1 = ip[NTHREADS + t];

    // Per-segment offset b (4-frame local recurrence, zero initial state)
    float b0 = w * x0.x;
    b0 = omw * b0 + w * x0.y;
    b0 = omw * b0 + w * x0.z;
    b0 = omw * b0 + w * x0.w;

    float b1 = w * x1.x;
    b1 = omw * b1 + w * x1.y;
    b1 = omw * b1 + w * x1.z;
    b1 = omw * b1 + w * x1.w;

    // Powers of q = (1-w)^4
    float q1 = omw * omw; q1 = q1 * q1;     // q
    const float q2  = q1 * q1;
    const float q4  = q2 * q2;
    const float q8  = q4 * q4;
    const float q16 = q8 * q8;
    const float Q   = q16 * q16;            // q^32  (per-warp aggregate decay)
    const float Q2  = Q * Q;
    const float Q4  = Q2 * Q2;
    const float Q8  = Q4 * Q4;              // q^256 (chunk0 block-total decay)

    // Kogge-Stone inclusive scan of b only (active lanes' multiplier is q^d)
    float ib0 = b0, ib1 = b1;
    {
        float p0, p1;
        p0 = __shfl_up_sync(0xffffffffu, ib0, 1);
        p1 = __shfl_up_sync(0xffffffffu, ib1, 1);
        if (lane >= 1)  { ib0 = q1  * p0 + ib0;  ib1 = q1  * p1 + ib1; }
        p0 = __shfl_up_sync(0xffffffffu, ib0, 2);
        p1 = __shfl_up_sync(0xffffffffu, ib1, 2);
        if (lane >= 2)  { ib0 = q2  * p0 + ib0;  ib1 = q2  * p1 + ib1; }
        p0 = __shfl_up_sync(0xffffffffu, ib0, 4);
        p1 = __shfl_up_sync(0xffffffffu, ib1, 4);
        if (lane >= 4)  { ib0 = q4  * p0 + ib0;  ib1 = q4  * p1 + ib1; }
        p0 = __shfl_up_sync(0xffffffffu, ib0, 8);
        p1 = __shfl_up_sync(0xffffffffu, ib1, 8);
        if (lane >= 8)  { ib0 = q8  * p0 + ib0;  ib1 = q8  * p1 + ib1; }
        p0 = __shfl_up_sync(0xffffffffu, ib0, 16);
        p1 = __shfl_up_sync(0xffffffffu, ib1, 16);
        if (lane >= 16) { ib0 = q16 * p0 + ib0;  ib1 = q16 * p1 + ib1; }
    }

    __shared__ float sb0[8], sb1[8];
    if (lane == 31) { sb0[warp] = ib0; sb1[warp] = ib1; }

    // In-warp exclusive b (shift by 1; lane 0 -> 0). Multiplier = q^lane.
    float eb0 = __shfl_up_sync(0xffffffffu, ib0, 1);
    float eb1 = __shfl_up_sync(0xffffffffu, ib1, 1);
    if (lane == 0) { eb0 = 0.0f; eb1 = 0.0f; }

    // q^lane and Q^warp via conditional multiplies (no shuffles)
    float ql = 1.0f;
    if (lane & 1)  ql *= q1;
    if (lane & 2)  ql *= q2;
    if (lane & 4)  ql *= q4;
    if (lane & 8)  ql *= q8;
    if (lane & 16) ql *= q16;
    float Qw = 1.0f;
    if (warp & 1) Qw *= Q;
    if (warp & 2) Qw *= Q2;
    if (warp & 4) Qw *= Q4;

    __syncthreads();

    // Cross-warp: exclusive b-prefix for this warp + chunk0 block-total b.
    float wpb0 = 0.0f, wpb1 = 0.0f, tb0 = 0.0f;
    #pragma unroll
    for (int k = 0; k < 8; ++k) {
        float s0 = sb0[k];
        if (k < warp) {
            wpb0 = Q * wpb0 + s0;
            wpb1 = Q * wpb1 + sb1[k];
        }
        tb0 = Q * tb0 + s0;
    }

    // Full exclusive transform for thread t: a = q^t = ql*Qw, b = ql*wpb + eb
    const float A  = ql * Qw;
    const float B0 = ql * wpb0 + eb0;
    const float B1 = ql * wpb1 + eb1;

    const float yinit = init_state[ch];
    float y0 = A * yinit + B0;                  // state entering chunk0
    const float ytot0 = Q8 * yinit + tb0;       // state after frame 1023
    float y1 = A * ytot0 + B1;                  // state entering chunk1

    // Replay exactly as the reference recurrence
    float4 o0, o1;
    y0 = w * x0.x + omw * y0; o0.x = y0;
    y0 = w * x0.y + omw * y0; o0.y = y0;
    y0 = w * x0.z + omw * y0; o0.z = y0;
    y0 = w * x0.w + omw * y0; o0.w = y0;

    y1 = w * x1.x + omw * y1; o1.x = y1;
    y1 = w * x1.y + omw * y1; o1.y = y1;
    y1 = w * x1.z + omw * y1; o1.z = y1;
    y1 = w * x1.w + omw * y1; o1.w = y1;

    float4* op = reinterpret_cast<float4*>(out + (size_t)ch * NFRAMES);
    op[t] = o0;
    op[NTHREADS + t] = o1;
}

extern "C" void kernel_launch(void* const* d_in, const int* in_sizes, int n_in,
                              void* d_out, int out_size)
{
    const float* input   = (const float*)d_in[0];
    const float* init_st = (const float*)d_in[1];
    const float* weight  = (const float*)d_in[2];
    float* out = (float*)d_out;

    ema_scan_kernel<<<NCHANNELS, NTHREADS>>>(input, init_st, weight, out);
}

// round 4
// speedup vs baseline: 1.1557x; 1.1557x over previous
#include <cuda_runtime.h>
#include <cuda_bf16.h>

// EMA scan y[n] = w*x[n] + (1-w)*y[n-1] over the contiguous frames axis (2048).
// input (16,8,256,2048) f32; initial_state (16,8,256); weight (8,256) clamped.
//
// Warp-autonomous: one warp per channel, 4 independent warps per CTA.
// The warp sweeps 2048 frames in 16 rounds of 128. In round k, lane l owns
// float4 index 32k+l (frames [128k+4l, 128k+4l+4)) -> perfectly coalesced
// LDG.128/STG.128. Each 4-frame segment is the affine map y -> r*y + b with
// the SAME r = (1-w)^4 for all lanes, so only the offset b is scanned
// (5 shuffles, multipliers r^d). Carry across rounds via lane-31 broadcast.
// No shared memory, no __syncthreads, no cross-warp epilogue.

#define NFRAMES   2048
#define NCHANNELS (16 * 8 * 256)
#define WARPS_PER_CTA 4
#define NROUNDS   16

__global__ __launch_bounds__(32 * WARPS_PER_CTA)
void ema_scan_kernel(const float* __restrict__ in,
                     const float* __restrict__ init_state,
                     const float* __restrict__ wt,
                     float* __restrict__ out)
{
    const int lane = threadIdx.x & 31;
    const int warp = threadIdx.x >> 5;
    const int ch   = blockIdx.x * WARPS_PER_CTA + warp;

    float w = wt[ch & 2047];
    w = fminf(fmaxf(w, 0.0f), 1.0f);
    const float omw = 1.0f - w;

    // Prefetch all 16 float4s (MLP = 16, fully coalesced)
    const float4* ip = reinterpret_cast<const float4*>(in + (size_t)ch * NFRAMES);
    float4 xs[NROUNDS];
    #pragma unroll
    for (int k = 0; k < NROUNDS; ++k)
        xs[k] = ip[k * 32 + lane];

    // Powers of r = (1-w)^4 (per-4-frame-segment decay)
    float r1 = omw * omw; r1 = r1 * r1;
    const float r2  = r1 * r1;
    const float r4  = r2 * r2;
    const float r8  = r4 * r4;
    const float r16 = r8 * r8;

    // r^lane (conditional multiplies, once), and r^(lane+1)
    float rl = 1.0f;
    if (lane & 1)  rl *= r1;
    if (lane & 2)  rl *= r2;
    if (lane & 4)  rl *= r4;
    if (lane & 8)  rl *= r8;
    if (lane & 16) rl *= r16;
    const float rlr = rl * r1;

    float ycarry = init_state[ch];

    float4* op = reinterpret_cast<float4*>(out + (size_t)ch * NFRAMES);

    #pragma unroll
    for (int k = 0; k < NROUNDS; ++k) {
        const float4 x = xs[k];

        // Segment offset: 4-frame local recurrence from zero state
        float b = w * x.x;
        b = omw * b + w * x.y;
        b = omw * b + w * x.z;
        b = omw * b + w * x.w;

        // Inclusive Kogge-Stone scan of b; active lanes' multiplier is r^d
        float p;
        p = __shfl_up_sync(0xffffffffu, b, 1);  if (lane >= 1)  b = r1  * p + b;
        p = __shfl_up_sync(0xffffffffu, b, 2);  if (lane >= 2)  b = r2  * p + b;
        p = __shfl_up_sync(0xffffffffu, b, 4);  if (lane >= 4)  b = r4  * p + b;
        p = __shfl_up_sync(0xffffffffu, b, 8);  if (lane >= 8)  b = r8  * p + b;
        p = __shfl_up_sync(0xffffffffu, b, 16); if (lane >= 16) b = r16 * p + b;

        // State after this lane's segment, entering state, and round carry
        const float yexit  = rlr * ycarry + b;
        float yenter = __shfl_up_sync(0xffffffffu, yexit, 1);
        if (lane == 0) yenter = ycarry;
        ycarry = __shfl_sync(0xffffffffu, yexit, 31);

        // Replay exactly as the reference recurrence
        float y = yenter;
        float4 o;
        y = w * x.x + omw * y; o.x = y;
        y = w * x.y + omw * y; o.y = y;
        y = w * x.z + omw * y; o.z = y;
        y = w * x.w + omw * y; o.w = y;

        op[k * 32 + lane] = o;
    }
}

extern "C" void kernel_launch(void* const* d_in, const int* in_sizes, int n_in,
                              void* d_out, int out_size)
{
    const float* input   = (const float*)d_in[0];
    const float* init_st = (const float*)d_in[1];
    const float* weight  = (const float*)d_in[2];
    float* out = (float*)d_out;

    ema_scan_kernel<<<NCHANNELS / WARPS_PER_CTA, 32 * WARPS_PER_CTA>>>(
        input, init_st, weight, out);
}